// round 11
// baseline (speedup 1.0000x reference)
#include <cuda_runtime.h>
#include <cstdint>

#define N_NODES 100000
#define HIDDEN  128
#define NPB     256   // nodes per CTA in GEMM kernel
#define CAP     48    // per-node edge bin capacity (Poisson mean 16; P(>=48)~1e-10)

// Scratch (device globals — allocation-free rule).
// INVARIANT: g_cnt[] and g_ovf_cnt are ZERO at kernel_launch entry
// (zero-init at module load; g_cnt re-zeroed inside k_gather_final,
//  g_ovf_cnt reset by k_fix).
__device__ __align__(16) float g_S [(size_t)N_NODES * HIDDEN];
__device__ __align__(16) float g_I [(size_t)N_NODES * HIDDEN];
__device__ int   g_cnt[N_NODES];
__device__ int   g_bin[(size_t)N_NODES * CAP];
__device__ int   g_ovf_cnt;
__device__ int   g_ovf[2 * 1600000];

__device__ __forceinline__ float sigmoidf(float v) {
    return 1.f / (1.f + __expf(-v));
}
__device__ __forceinline__ uint32_t to_tf32(float f) {
    uint32_t u;
    asm("cvt.rna.tf32.f32 %0, %1;" : "=r"(u) : "f"(f));
    return u;
}
__device__ __forceinline__ void mma_tf32(float* c, uint32_t a0, uint32_t a1,
                                         uint32_t a2, uint32_t a3,
                                         uint32_t b0, uint32_t b1) {
    asm volatile(
        "mma.sync.aligned.m16n8k8.row.col.f32.tf32.tf32.f32 "
        "{%0,%1,%2,%3}, {%4,%5,%6,%7}, {%8,%9}, {%0,%1,%2,%3};"
        : "+f"(c[0]), "+f"(c[1]), "+f"(c[2]), "+f"(c[3])
        : "r"(a0), "r"(a1), "r"(a2), "r"(a3), "r"(b0), "r"(b1));
}

// Shared layout (uint32 elements):
//   xs [256][132]  node-major tf32 x tile; REUSED as fp32 sigmoid bounce
//   Ws [128][132]  o-major tf32 W   (col-major B for mma: B[n][k])
//   sgam[256], sbias[128] as floats
#define XS_SZ   (256 * 132)
#define WS_SZ   (128 * 132)
#define SM_U32  (XS_SZ + WS_SZ + 256 + 128)

// ---------------------------------------------------------------------------
// K1: tf32 mma.sync sigmoid-GEMM. 512 threads = 16 warps; warp w computes
// nodes [w*16, w*16+16) x all 128 outputs, K=128 in 16 k-steps.
// Epilogue bounces D through smem -> ALL global stores coalesced STG.128.
// Fuses: g_S, g_I (both fp32), out[2] = gamma*I, out[3] = 0.
// ---------------------------------------------------------------------------
__global__ __launch_bounds__(512, 1) void k_gemm(
    const float* __restrict__ x, const float* __restrict__ W,
    const float* __restrict__ b, float* __restrict__ out)
{
    extern __shared__ uint32_t sh[];
    uint32_t* xs    = sh;
    uint32_t* Ws    = sh + XS_SZ;
    float*    sgam  = reinterpret_cast<float*>(sh + XS_SZ + WS_SZ);
    float*    sbias = sgam + 256;
    float*    bounce = reinterpret_cast<float*>(xs);   // alias, used post-MMA

    const int tid  = threadIdx.x;
    const int warp = tid >> 5;
    const int lane = tid & 31;
    const int grp  = lane >> 2;   // 0..7
    const int qk   = lane & 3;    // 0..3
    const int base = blockIdx.x * NPB;
    const int nn   = min(NPB, N_NODES - base);
    const int m0   = warp * 16;

    // Ws[o*132 + h] = tf32(W[o*128 + h])   — float4 LDG, uint4 STS
    {
        const float4* Wsrc = reinterpret_cast<const float4*>(W);
        for (int idx = tid; idx < HIDDEN * 32; idx += 512) {
            const int o = idx >> 5, q = idx & 31;
            const float4 v = Wsrc[idx];
            uint4 u;
            u.x = to_tf32(v.x); u.y = to_tf32(v.y);
            u.z = to_tf32(v.z); u.w = to_tf32(v.w);
            *reinterpret_cast<uint4*>(&Ws[o * 132 + q * 4]) = u;
        }
    }
    if (tid < HIDDEN) sbias[tid] = b[tid];
    // gamma = x[3, node, 1]
    for (int n = tid; n < NPB; n += 512) {
        sgam[n] = (n < nn)
            ? x[((size_t)3 * N_NODES + base + n) * HIDDEN + 1] : 0.f;
    }

    for (int s = 0; s < 2; ++s) {
        // xs[n*132 + h] = tf32(x[s, base+n, h]); rows >= nn read the next
        // s-slice (in-bounds of x, results discarded).
        const float4* xsrc = reinterpret_cast<const float4*>(
            x + ((size_t)s * N_NODES + base) * HIDDEN);
        __syncthreads();   // prior consumers of xs/bounce done
        for (int idx = tid; idx < NPB * 32; idx += 512) {
            const int n = idx >> 5, q = idx & 31;
            const float4 v = xsrc[idx];
            uint4 u;
            u.x = to_tf32(v.x); u.y = to_tf32(v.y);
            u.z = to_tf32(v.z); u.w = to_tf32(v.w);
            *reinterpret_cast<uint4*>(&xs[n * 132 + q * 4]) = u;
        }
        __syncthreads();

        float acc[16][4];
        #pragma unroll
        for (int nb = 0; nb < 16; ++nb)
            #pragma unroll
            for (int i = 0; i < 4; ++i) acc[nb][i] = 0.f;

        const uint32_t* xrow0 = xs + (m0 + grp) * 132;       // rows m0+grp
        const uint32_t* xrow1 = xrow0 + 8 * 132;             // rows m0+grp+8

        #pragma unroll 2
        for (int k0 = 0; k0 < 16; ++k0) {
            const int kb = k0 * 8;
            const uint32_t a0 = xrow0[kb + qk];
            const uint32_t a1 = xrow1[kb + qk];
            const uint32_t a2 = xrow0[kb + qk + 4];
            const uint32_t a3 = xrow1[kb + qk + 4];
            #pragma unroll
            for (int nb = 0; nb < 16; ++nb) {
                const uint32_t* wrow = Ws + (nb * 8 + grp) * 132 + kb;
                mma_tf32(acc[nb], a0, a1, a2, a3, wrow[qk], wrow[qk + 4]);
            }
        }
        __syncthreads();   // all MMA reads of xs complete before bounce reuse

        // Fragment -> smem bounce (sigmoid applied here)
        {
            const int r0 = m0 + grp, r1 = r0 + 8;
            #pragma unroll
            for (int nb = 0; nb < 16; ++nb) {
                const int col = nb * 8 + 2 * qk;
                const float b0 = sbias[col], b1 = sbias[col + 1];
                *reinterpret_cast<float2*>(&bounce[r0 * 132 + col]) =
                    make_float2(sigmoidf(acc[nb][0] + b0), sigmoidf(acc[nb][1] + b1));
                *reinterpret_cast<float2*>(&bounce[r1 * 132 + col]) =
                    make_float2(sigmoidf(acc[nb][2] + b0), sigmoidf(acc[nb][3] + b1));
            }
        }
        __syncthreads();

        // Cooperative coalesced stores from bounce
        if (s == 0) {
            for (int idx = tid; idx < nn * 32; idx += 512) {
                const int n = idx >> 5, q = idx & 31;
                const float4 v = *reinterpret_cast<const float4*>(&bounce[n * 132 + q * 4]);
                *reinterpret_cast<float4*>(&g_S[((size_t)(base + n)) * HIDDEN + q * 4]) = v;
            }
        } else {
            for (int idx = tid; idx < nn * 32; idx += 512) {
                const int n = idx >> 5, q = idx & 31;
                const int node = base + n;
                const float4 v = *reinterpret_cast<const float4*>(&bounce[n * 132 + q * 4]);
                const size_t off = (size_t)node * HIDDEN + q * 4;
                *reinterpret_cast<float4*>(&g_I[off]) = v;
                const float gm = sgam[n];
                *reinterpret_cast<float4*>(&out[(size_t)2 * N_NODES * HIDDEN + off])
                    = make_float4(gm * v.x, gm * v.y, gm * v.z, gm * v.w);
                *reinterpret_cast<float4*>(&out[(size_t)3 * N_NODES * HIDDEN + off])
                    = make_float4(0.f, 0.f, 0.f, 0.f);
            }
        }
    }
}

// ---------------------------------------------------------------------------
// K2: bin edges by destination row (indices are int32 per JAX default x64-off).
// ---------------------------------------------------------------------------
__global__ __launch_bounds__(256) void k_place(
    const int* __restrict__ rows, const int* __restrict__ cols, int n_edges)
{
    const int i = blockIdx.x * 256 + threadIdx.x;
    if (i >= n_edges) return;
    int r = rows[i], c = cols[i];
    r = min(max(r, 0), N_NODES - 1);
    c = min(max(c, 0), N_NODES - 1);
    const int slot = atomicAdd(&g_cnt[r], 1);
    if (slot < CAP) {
        g_bin[(size_t)r * CAP + slot] = c;
    } else {
        const int o = atomicAdd(&g_ovf_cnt, 1);
        g_ovf[2 * o] = r;
        g_ovf[2 * o + 1] = c;
    }
}

// ---------------------------------------------------------------------------
// K3: gather + finalize (r7-proven fp32 path). Warp per node, MLP=8:
//     AI = sum I[col];  dS = -beta*AI*S ; dI = -dS - gamma*I.
//     Re-zeroes g_cnt[node] for the next call.
// ---------------------------------------------------------------------------
__global__ __launch_bounds__(256) void k_gather_final(
    const float* __restrict__ x, float* __restrict__ out)
{
    const int node = (blockIdx.x * 256 + threadIdx.x) >> 5;
    if (node >= N_NODES) return;
    const int lane = threadIdx.x & 31;

    const int d = min(g_cnt[node], CAP);
    if (lane == 0) g_cnt[node] = 0;   // reset for next call/replay
    const int* __restrict__ bin = g_bin + (size_t)node * CAP;
    const float4* __restrict__ I4 = reinterpret_cast<const float4*>(g_I);

    float4 a = make_float4(0.f, 0.f, 0.f, 0.f);
    int i = 0;
    for (; i + 8 <= d; i += 8) {      // 8 outstanding 512B L2 loads per warp
        int c[8];
        #pragma unroll
        for (int k = 0; k < 8; ++k) c[k] = __ldg(&bin[i + k]);
        float4 v[8];
        #pragma unroll
        for (int k = 0; k < 8; ++k) v[k] = I4[(size_t)c[k] * 32 + lane];
        #pragma unroll
        for (int k = 0; k < 8; ++k) {
            a.x += v[k].x; a.y += v[k].y; a.z += v[k].z; a.w += v[k].w;
        }
    }
    if (i + 4 <= d) {
        int c[4];
        #pragma unroll
        for (int k = 0; k < 4; ++k) c[k] = __ldg(&bin[i + k]);
        float4 v[4];
        #pragma unroll
        for (int k = 0; k < 4; ++k) v[k] = I4[(size_t)c[k] * 32 + lane];
        #pragma unroll
        for (int k = 0; k < 4; ++k) {
            a.x += v[k].x; a.y += v[k].y; a.z += v[k].z; a.w += v[k].w;
        }
        i += 4;
    }
    for (; i < d; ++i) {
        const float4 v = I4[(size_t)__ldg(&bin[i]) * 32 + lane];
        a.x += v.x; a.y += v.y; a.z += v.z; a.w += v.w;
    }

    const float beta = x[((size_t)3 * N_NODES + node) * HIDDEN];
    const size_t fo = (size_t)node * 32 + lane;
    const float4 S4 = reinterpret_cast<const float4*>(g_S)[fo];
    const float4 G4 = reinterpret_cast<const float4*>(
        out + (size_t)2 * N_NODES * HIDDEN)[fo];

    float4 dS, dI;
    dS.x = -beta * a.x * S4.x;  dI.x = -dS.x - G4.x;
    dS.y = -beta * a.y * S4.y;  dI.y = -dS.y - G4.y;
    dS.z = -beta * a.z * S4.z;  dI.z = -dS.z - G4.z;
    dS.w = -beta * a.w * S4.w;  dI.w = -dS.w - G4.w;

    reinterpret_cast<float4*>(out)[fo] = dS;
    reinterpret_cast<float4*>(out + (size_t)N_NODES * HIDDEN)[fo] = dI;
}

// ---------------------------------------------------------------------------
// K4: overflow fix-up (expected empty) + reset g_ovf_cnt for next call.
// ---------------------------------------------------------------------------
__global__ __launch_bounds__(256) void k_fix(
    const float* __restrict__ x, float* __restrict__ out)
{
    const int n = g_ovf_cnt;
    if (n > 0) {
        const long long total = (long long)n * HIDDEN;
        const int stride = gridDim.x * 256;
        for (long long idx = blockIdx.x * 256 + threadIdx.x; idx < total;
             idx += stride) {
            const int e = (int)(idx >> 7);
            const int j = (int)(idx & 127);
            const int r = g_ovf[2 * e];
            const int c = g_ovf[2 * e + 1];
            const float v = g_I[(size_t)c * HIDDEN + j];
            const float beta = x[((size_t)3 * N_NODES + r) * HIDDEN];
            const float delta = -beta * v * g_S[(size_t)r * HIDDEN + j];
            atomicAdd(&out[(size_t)r * HIDDEN + j], delta);
            atomicAdd(&out[(size_t)N_NODES * HIDDEN + (size_t)r * HIDDEN + j], -delta);
        }
    }
    if (blockIdx.x == 0 && threadIdx.x == 0) g_ovf_cnt = 0;
}

// ---------------------------------------------------------------------------
extern "C" void kernel_launch(void* const* d_in, const int* in_sizes, int n_in,
                              void* d_out, int out_size)
{
    const float* x    = (const float*)d_in[0];
    const float* W    = (const float*)d_in[1];
    const float* b    = (const float*)d_in[2];
    const int*   rows = (const int*)d_in[3];
    const int*   cols = (const int*)d_in[4];
    float*       out  = (float*)d_out;

    const int n_edges = in_sizes[3];

    const size_t smem = (size_t)SM_U32 * sizeof(uint32_t);
    cudaFuncSetAttribute(k_gemm, cudaFuncAttributeMaxDynamicSharedMemorySize,
                         (int)smem);

    k_place<<<(n_edges + 255) / 256, 256>>>(rows, cols, n_edges);

    const int gemm_blocks = (N_NODES + NPB - 1) / NPB;
    k_gemm<<<gemm_blocks, 512, smem>>>(x, W, b, out);

    const int gf_blocks = (N_NODES * 32 + 255) / 256;  // warp per node
    k_gather_final<<<gf_blocks, 256>>>(x, out);

    k_fix<<<16, 256>>>(x, out);
}

// round 13
// speedup vs baseline: 1.5770x; 1.5770x over previous
#include <cuda_runtime.h>
#include <cuda_fp16.h>
#include <cstdint>

#define N_NODES 100000
#define HIDDEN  128
#define NPB     256   // nodes per CTA in GEMM kernel
#define CAP     48    // per-node edge bin capacity (Poisson mean 16; P(>=48)~1e-10)

// Scratch (device globals — allocation-free rule).
// INVARIANT: g_cnt[] and g_ovf_cnt are ZERO at kernel_launch entry
// (zero-init at module load; re-zeroed at the end of every call by k_fix).
__device__ __align__(16) float   g_S  [(size_t)N_NODES * HIDDEN];
__device__ __align__(16) float   g_I  [(size_t)N_NODES * HIDDEN];
__device__ int   g_cnt[N_NODES];
__device__ int   g_bin[(size_t)N_NODES * CAP];
__device__ int   g_ovf_cnt;
__device__ int   g_ovf[2 * 1600000];

__device__ __forceinline__ float sigmoidf(float v) {
    return 1.f / (1.f + __expf(-v));
}
__device__ __forceinline__ uint32_t to_tf32(float f) {
    uint32_t u;
    asm("cvt.rna.tf32.f32 %0, %1;" : "=r"(u) : "f"(f));
    return u;
}
__device__ __forceinline__ void mma_tf32(float* c, uint32_t a0, uint32_t a1,
                                         uint32_t a2, uint32_t a3,
                                         uint32_t b0, uint32_t b1) {
    asm volatile(
        "mma.sync.aligned.m16n8k8.row.col.f32.tf32.tf32.f32 "
        "{%0,%1,%2,%3}, {%4,%5,%6,%7}, {%8,%9}, {%0,%1,%2,%3};"
        : "+f"(c[0]), "+f"(c[1]), "+f"(c[2]), "+f"(c[3])
        : "r"(a0), "r"(a1), "r"(a2), "r"(a3), "r"(b0), "r"(b1));
}

// Shared layout (uint32 elements):
//   xs [256][132]  node-major tf32 x tile
//   Ws [128][132]  o-major tf32 W   (col-major B for mma: B[n][k])
//   sgam[256], sbias[128] as floats
#define XS_SZ   (256 * 132)
#define WS_SZ   (128 * 132)
#define SM_U32  (XS_SZ + WS_SZ + 256 + 128)

// ---------------------------------------------------------------------------
// K1: tf32 mma.sync sigmoid-GEMM. 512 threads = 16 warps; warp w computes
// nodes [w*16, w*16+16) x all 128 outputs, K=128 in 16 k-steps.
// Fuses: g_S, g_I, out[2] = gamma*I, out[3] = 0.
// ---------------------------------------------------------------------------
__global__ __launch_bounds__(512, 1) void k_gemm(
    const float* __restrict__ x, const float* __restrict__ W,
    const float* __restrict__ b, float* __restrict__ out)
{
    extern __shared__ uint32_t sh[];
    uint32_t* xs    = sh;
    uint32_t* Ws    = sh + XS_SZ;
    float*    sgam  = reinterpret_cast<float*>(sh + XS_SZ + WS_SZ);
    float*    sbias = sgam + 256;

    const int tid  = threadIdx.x;
    const int warp = tid >> 5;
    const int lane = tid & 31;
    const int grp  = lane >> 2;   // 0..7
    const int qk   = lane & 3;    // 0..3
    const int base = blockIdx.x * NPB;
    const int nn   = min(NPB, N_NODES - base);
    const int m0   = warp * 16;

    // Ws[o*132 + h] = tf32(W[o*128 + h])   (B col-major: B[n][k])
    for (int idx = tid; idx < HIDDEN * HIDDEN; idx += 512) {
        Ws[(idx >> 7) * 132 + (idx & 127)] = to_tf32(W[idx]);
    }
    if (tid < HIDDEN) sbias[tid] = b[tid];
    // gamma = x[3, node, 1]
    for (int n = tid; n < NPB; n += 512) {
        sgam[n] = (n < nn)
            ? x[((size_t)3 * N_NODES + base + n) * HIDDEN + 1] : 0.f;
    }

    for (int s = 0; s < 2; ++s) {
        // xs[n*132 + h] = tf32(x[s, base+n, h]); rows >= nn read into the
        // next s-slice (in-bounds of x, results discarded).
        const float* xsrc = x + ((size_t)s * N_NODES + base) * HIDDEN;
        __syncthreads();   // previous-iter consumers done before overwrite
        for (int idx = tid; idx < NPB * HIDDEN; idx += 512) {
            xs[(idx >> 7) * 132 + (idx & 127)] = to_tf32(xsrc[idx]);
        }
        __syncthreads();

        float acc[16][4];
        #pragma unroll
        for (int nb = 0; nb < 16; ++nb)
            #pragma unroll
            for (int i = 0; i < 4; ++i) acc[nb][i] = 0.f;

        const uint32_t* xrow0 = xs + (m0 + grp) * 132;       // rows m0+grp
        const uint32_t* xrow1 = xrow0 + 8 * 132;             // rows m0+grp+8

        #pragma unroll 2
        for (int k0 = 0; k0 < 16; ++k0) {
            const int kb = k0 * 8;
            const uint32_t a0 = xrow0[kb + qk];
            const uint32_t a1 = xrow1[kb + qk];
            const uint32_t a2 = xrow0[kb + qk + 4];
            const uint32_t a3 = xrow1[kb + qk + 4];
            #pragma unroll
            for (int nb = 0; nb < 16; ++nb) {
                const uint32_t* wrow = Ws + (nb * 8 + grp) * 132 + kb;
                mma_tf32(acc[nb], a0, a1, a2, a3, wrow[qk], wrow[qk + 4]);
            }
        }

        // Epilogue: thread owns rows r0 = m0+grp, r1 = r0+8;
        // per nb, cols nb*8 + 2*qk (+1): float2 stores, 32B-sector coalesced.
        const int r0 = m0 + grp, r1 = r0 + 8;
        const float gm0 = sgam[r0], gm1 = sgam[r1];
        #pragma unroll
        for (int nb = 0; nb < 16; ++nb) {
            const int col = nb * 8 + 2 * qk;
            const float b0 = sbias[col], b1 = sbias[col + 1];
            const float v00 = sigmoidf(acc[nb][0] + b0);
            const float v01 = sigmoidf(acc[nb][1] + b1);
            const float v10 = sigmoidf(acc[nb][2] + b0);
            const float v11 = sigmoidf(acc[nb][3] + b1);
            const size_t o0 = ((size_t)(base + r0)) * HIDDEN + col;
            const size_t o1 = ((size_t)(base + r1)) * HIDDEN + col;
            if (s == 0) {
                if (r0 < nn) *reinterpret_cast<float2*>(&g_S[o0]) = make_float2(v00, v01);
                if (r1 < nn) *reinterpret_cast<float2*>(&g_S[o1]) = make_float2(v10, v11);
            } else {
                if (r0 < nn) {
                    *reinterpret_cast<float2*>(&g_I[o0]) = make_float2(v00, v01);
                    *reinterpret_cast<float2*>(&out[(size_t)2 * N_NODES * HIDDEN + o0])
                        = make_float2(gm0 * v00, gm0 * v01);
                    *reinterpret_cast<float2*>(&out[(size_t)3 * N_NODES * HIDDEN + o0])
                        = make_float2(0.f, 0.f);
                }
                if (r1 < nn) {
                    *reinterpret_cast<float2*>(&g_I[o1]) = make_float2(v10, v11);
                    *reinterpret_cast<float2*>(&out[(size_t)2 * N_NODES * HIDDEN + o1])
                        = make_float2(gm1 * v10, gm1 * v11);
                    *reinterpret_cast<float2*>(&out[(size_t)3 * N_NODES * HIDDEN + o1])
                        = make_float2(0.f, 0.f);
                }
            }
        }
    }
}

// ---------------------------------------------------------------------------
// K2: bin edges by destination row (indices are int32 per JAX default x64-off).
// ---------------------------------------------------------------------------
__global__ __launch_bounds__(256) void k_place(
    const int* __restrict__ rows, const int* __restrict__ cols, int n_edges)
{
    const int i = blockIdx.x * 256 + threadIdx.x;
    if (i >= n_edges) return;
    int r = rows[i], c = cols[i];
    r = min(max(r, 0), N_NODES - 1);
    c = min(max(c, 0), N_NODES - 1);
    const int slot = atomicAdd(&g_cnt[r], 1);
    if (slot < CAP) {
        g_bin[(size_t)r * CAP + slot] = c;
    } else {
        const int o = atomicAdd(&g_ovf_cnt, 1);
        g_ovf[2 * o] = r;
        g_ovf[2 * o + 1] = c;
    }
}

// ---------------------------------------------------------------------------
// K3: gather + finalize. Warp per node, MLP=8: AI = sum_{in-edges} I[col],
//     dS = -beta*AI*S ; dI = -dS - gamma*I. No float atomics.
// ---------------------------------------------------------------------------
__global__ __launch_bounds__(256) void k_gather_final(
    const float* __restrict__ x, float* __restrict__ out)
{
    const int node = (blockIdx.x * 256 + threadIdx.x) >> 5;
    if (node >= N_NODES) return;
    const int lane = threadIdx.x & 31;

    const int d = min(g_cnt[node], CAP);
    const int* __restrict__ bin = g_bin + (size_t)node * CAP;
    const float4* __restrict__ I4 = reinterpret_cast<const float4*>(g_I);

    float4 a = make_float4(0.f, 0.f, 0.f, 0.f);
    int i = 0;
    for (; i + 8 <= d; i += 8) {      // 8 outstanding 512B L2 loads per warp
        int c[8];
        #pragma unroll
        for (int k = 0; k < 8; ++k) c[k] = __ldg(&bin[i + k]);
        float4 v[8];
        #pragma unroll
        for (int k = 0; k < 8; ++k) v[k] = I4[(size_t)c[k] * 32 + lane];
        #pragma unroll
        for (int k = 0; k < 8; ++k) {
            a.x += v[k].x; a.y += v[k].y; a.z += v[k].z; a.w += v[k].w;
        }
    }
    if (i + 4 <= d) {
        int c[4];
        #pragma unroll
        for (int k = 0; k < 4; ++k) c[k] = __ldg(&bin[i + k]);
        float4 v[4];
        #pragma unroll
        for (int k = 0; k < 4; ++k) v[k] = I4[(size_t)c[k] * 32 + lane];
        #pragma unroll
        for (int k = 0; k < 4; ++k) {
            a.x += v[k].x; a.y += v[k].y; a.z += v[k].z; a.w += v[k].w;
        }
        i += 4;
    }
    for (; i < d; ++i) {
        const float4 v = I4[(size_t)__ldg(&bin[i]) * 32 + lane];
        a.x += v.x; a.y += v.y; a.z += v.z; a.w += v.w;
    }

    const float beta = x[((size_t)3 * N_NODES + node) * HIDDEN];
    const size_t fo = (size_t)node * 32 + lane;
    const float4 S4 = reinterpret_cast<const float4*>(g_S)[fo];
    const float4 G4 = reinterpret_cast<const float4*>(
        out + (size_t)2 * N_NODES * HIDDEN)[fo];

    float4 dS, dI;
    dS.x = -beta * a.x * S4.x;  dI.x = -dS.x - G4.x;
    dS.y = -beta * a.y * S4.y;  dI.y = -dS.y - G4.y;
    dS.z = -beta * a.z * S4.z;  dI.z = -dS.z - G4.z;
    dS.w = -beta * a.w * S4.w;  dI.w = -dS.w - G4.w;

    reinterpret_cast<float4*>(out)[fo] = dS;
    reinterpret_cast<float4*>(out + (size_t)N_NODES * HIDDEN)[fo] = dI;
}

// ---------------------------------------------------------------------------
// K4: overflow fix-up (expected empty) + re-zero counters for next call.
// ---------------------------------------------------------------------------
__global__ __launch_bounds__(256) void k_fix(
    const float* __restrict__ x, float* __restrict__ out)
{
    if (blockIdx.x == 0) {
        const int n = g_ovf_cnt;
        if (n > 0) {
            const long long total = (long long)n * HIDDEN;
            for (long long idx = threadIdx.x; idx < total; idx += 256) {
                const int e = (int)(idx >> 7);
                const int j = (int)(idx & 127);
                const int r = g_ovf[2 * e];
                const int c = g_ovf[2 * e + 1];
                const float v = g_I[(size_t)c * HIDDEN + j];
                const float beta = x[((size_t)3 * N_NODES + r) * HIDDEN];
                const float delta = -beta * v * g_S[(size_t)r * HIDDEN + j];
                atomicAdd(&out[(size_t)r * HIDDEN + j], delta);
                atomicAdd(&out[(size_t)N_NODES * HIDDEN + (size_t)r * HIDDEN + j], -delta);
            }
        }
        __syncthreads();
        if (threadIdx.x == 0) g_ovf_cnt = 0;
    }
    for (int i = blockIdx.x * 256 + threadIdx.x; i < N_NODES;
         i += gridDim.x * 256) {
        g_cnt[i] = 0;
    }
}

// ---------------------------------------------------------------------------
extern "C" void kernel_launch(void* const* d_in, const int* in_sizes, int n_in,
                              void* d_out, int out_size)
{
    const float* x    = (const float*)d_in[0];
    const float* W    = (const float*)d_in[1];
    const float* b    = (const float*)d_in[2];
    const int*   rows = (const int*)d_in[3];
    const int*   cols = (const int*)d_in[4];
    float*       out  = (float*)d_out;

    const int n_edges = in_sizes[3];

    const size_t smem = (size_t)SM_U32 * sizeof(uint32_t);
    cudaFuncSetAttribute(k_gemm, cudaFuncAttributeMaxDynamicSharedMemorySize,
                         (int)smem);

    k_place<<<(n_edges + 255) / 256, 256>>>(rows, cols, n_edges);

    const int gemm_blocks = (N_NODES + NPB - 1) / NPB;
    k_gemm<<<gemm_blocks, 512, smem>>>(x, W, b, out);

    const int gf_blocks = (N_NODES * 32 + 255) / 256;  // warp per node
    k_gather_final<<<gf_blocks, 256>>>(x, out);

    k_fix<<<128, 256>>>(x, out);
}

// round 14
// speedup vs baseline: 2.0140x; 1.2771x over previous
#include <cuda_runtime.h>
#include <cuda_fp16.h>
#include <cstdint>

#define N_NODES 100000
#define HIDDEN  128
#define NPB     256   // nodes per CTA in GEMM kernel
#define CAP     48    // per-node edge bin capacity (Poisson mean 16; P(>=48)~1e-10)

// Scratch (device globals — allocation-free rule).
// INVARIANT: g_cnt[] and g_ovf_cnt are ZERO at kernel_launch entry
// (zero-init at module load; re-zeroed at the end of every call by k_fix).
__device__ __align__(16) float   g_S  [(size_t)N_NODES * HIDDEN];
__device__ __align__(16) float   g_I  [(size_t)N_NODES * HIDDEN];
__device__ __align__(16) __half2 g_Ih [(size_t)N_NODES * (HIDDEN / 2)];
__device__ int   g_cnt[N_NODES];
__device__ int   g_bin[(size_t)N_NODES * CAP];
__device__ int   g_ovf_cnt;
__device__ int   g_ovf[2 * 1600000];

__device__ __forceinline__ float sigmoidf(float v) {
    return 1.f / (1.f + __expf(-v));
}
__device__ __forceinline__ uint32_t to_tf32(float f) {
    uint32_t u;
    asm("cvt.rna.tf32.f32 %0, %1;" : "=r"(u) : "f"(f));
    return u;
}
__device__ __forceinline__ void mma_tf32(float* c, uint32_t a0, uint32_t a1,
                                         uint32_t a2, uint32_t a3,
                                         uint32_t b0, uint32_t b1) {
    asm volatile(
        "mma.sync.aligned.m16n8k8.row.col.f32.tf32.tf32.f32 "
        "{%0,%1,%2,%3}, {%4,%5,%6,%7}, {%8,%9}, {%0,%1,%2,%3};"
        : "+f"(c[0]), "+f"(c[1]), "+f"(c[2]), "+f"(c[3])
        : "r"(a0), "r"(a1), "r"(a2), "r"(a3), "r"(b0), "r"(b1));
}

// Shared layout (uint32 elements):
//   xs [256][132]  node-major tf32 x tile
//   Ws [128][132]  o-major tf32 W   (col-major B for mma: B[n][k])
//   sgam[256], sbias[128] as floats
#define XS_SZ   (256 * 132)
#define WS_SZ   (128 * 132)
#define SM_U32  (XS_SZ + WS_SZ + 256 + 128)

// ---------------------------------------------------------------------------
// K1: tf32 mma.sync sigmoid-GEMM (r7-proven, unmodified). 512 threads;
// warp w: nodes [w*16, w*16+16) x 128 outputs, K=128 in 16 k-steps.
// Fuses: g_S, g_I, out[2] = gamma*I, out[3] = 0.
// ---------------------------------------------------------------------------
__global__ __launch_bounds__(512, 1) void k_gemm(
    const float* __restrict__ x, const float* __restrict__ W,
    const float* __restrict__ b, float* __restrict__ out)
{
    extern __shared__ uint32_t sh[];
    uint32_t* xs    = sh;
    uint32_t* Ws    = sh + XS_SZ;
    float*    sgam  = reinterpret_cast<float*>(sh + XS_SZ + WS_SZ);
    float*    sbias = sgam + 256;

    const int tid  = threadIdx.x;
    const int warp = tid >> 5;
    const int lane = tid & 31;
    const int grp  = lane >> 2;   // 0..7
    const int qk   = lane & 3;    // 0..3
    const int base = blockIdx.x * NPB;
    const int nn   = min(NPB, N_NODES - base);
    const int m0   = warp * 16;

    // Ws[o*132 + h] = tf32(W[o*128 + h])   (B col-major: B[n][k])
    for (int idx = tid; idx < HIDDEN * HIDDEN; idx += 512) {
        Ws[(idx >> 7) * 132 + (idx & 127)] = to_tf32(W[idx]);
    }
    if (tid < HIDDEN) sbias[tid] = b[tid];
    // gamma = x[3, node, 1]
    for (int n = tid; n < NPB; n += 512) {
        sgam[n] = (n < nn)
            ? x[((size_t)3 * N_NODES + base + n) * HIDDEN + 1] : 0.f;
    }

    for (int s = 0; s < 2; ++s) {
        // xs[n*132 + h] = tf32(x[s, base+n, h]); rows >= nn read into the
        // next s-slice (in-bounds of x, results discarded).
        const float* xsrc = x + ((size_t)s * N_NODES + base) * HIDDEN;
        __syncthreads();   // previous-iter consumers done before overwrite
        for (int idx = tid; idx < NPB * HIDDEN; idx += 512) {
            xs[(idx >> 7) * 132 + (idx & 127)] = to_tf32(xsrc[idx]);
        }
        __syncthreads();

        float acc[16][4];
        #pragma unroll
        for (int nb = 0; nb < 16; ++nb)
            #pragma unroll
            for (int i = 0; i < 4; ++i) acc[nb][i] = 0.f;

        const uint32_t* xrow0 = xs + (m0 + grp) * 132;       // rows m0+grp
        const uint32_t* xrow1 = xrow0 + 8 * 132;             // rows m0+grp+8

        #pragma unroll 2
        for (int k0 = 0; k0 < 16; ++k0) {
            const int kb = k0 * 8;
            const uint32_t a0 = xrow0[kb + qk];
            const uint32_t a1 = xrow1[kb + qk];
            const uint32_t a2 = xrow0[kb + qk + 4];
            const uint32_t a3 = xrow1[kb + qk + 4];
            #pragma unroll
            for (int nb = 0; nb < 16; ++nb) {
                const uint32_t* wrow = Ws + (nb * 8 + grp) * 132 + kb;
                mma_tf32(acc[nb], a0, a1, a2, a3, wrow[qk], wrow[qk + 4]);
            }
        }

        // Epilogue: thread owns rows r0 = m0+grp, r1 = r0+8;
        // per nb, cols nb*8 + 2*qk (+1): float2 stores, 32B-sector coalesced.
        const int r0 = m0 + grp, r1 = r0 + 8;
        const float gm0 = sgam[r0], gm1 = sgam[r1];
        #pragma unroll
        for (int nb = 0; nb < 16; ++nb) {
            const int col = nb * 8 + 2 * qk;
            const float b0 = sbias[col], b1 = sbias[col + 1];
            const float v00 = sigmoidf(acc[nb][0] + b0);
            const float v01 = sigmoidf(acc[nb][1] + b1);
            const float v10 = sigmoidf(acc[nb][2] + b0);
            const float v11 = sigmoidf(acc[nb][3] + b1);
            const size_t o0 = ((size_t)(base + r0)) * HIDDEN + col;
            const size_t o1 = ((size_t)(base + r1)) * HIDDEN + col;
            if (s == 0) {
                if (r0 < nn) *reinterpret_cast<float2*>(&g_S[o0]) = make_float2(v00, v01);
                if (r1 < nn) *reinterpret_cast<float2*>(&g_S[o1]) = make_float2(v10, v11);
            } else {
                if (r0 < nn) {
                    *reinterpret_cast<float2*>(&g_I[o0]) = make_float2(v00, v01);
                    *reinterpret_cast<float2*>(&out[(size_t)2 * N_NODES * HIDDEN + o0])
                        = make_float2(gm0 * v00, gm0 * v01);
                    *reinterpret_cast<float2*>(&out[(size_t)3 * N_NODES * HIDDEN + o0])
                        = make_float2(0.f, 0.f);
                }
                if (r1 < nn) {
                    *reinterpret_cast<float2*>(&g_I[o1]) = make_float2(v10, v11);
                    *reinterpret_cast<float2*>(&out[(size_t)2 * N_NODES * HIDDEN + o1])
                        = make_float2(gm1 * v10, gm1 * v11);
                    *reinterpret_cast<float2*>(&out[(size_t)3 * N_NODES * HIDDEN + o1])
                        = make_float2(0.f, 0.f);
                }
            }
        }
    }
}

// ---------------------------------------------------------------------------
// K1b: build fp16 mirror of I (separate kernel — GEMM epilogue untouched).
//      51 MB read + 26 MB write, coalesced; ~10 us.
// ---------------------------------------------------------------------------
__global__ __launch_bounds__(256) void k_mirror()
{
    const size_t total = (size_t)N_NODES * 32;   // float4 / uint2 elements
    const size_t stride = (size_t)gridDim.x * 256;
    uint2* Ih = reinterpret_cast<uint2*>(g_Ih);
    const float4* I4 = reinterpret_cast<const float4*>(g_I);
    for (size_t i = (size_t)blockIdx.x * 256 + threadIdx.x; i < total; i += stride) {
        const float4 v = I4[i];
        const __half2 h0 = __floats2half2_rn(v.x, v.y);
        const __half2 h1 = __floats2half2_rn(v.z, v.w);
        uint2 u;
        u.x = *reinterpret_cast<const unsigned*>(&h0);
        u.y = *reinterpret_cast<const unsigned*>(&h1);
        Ih[i] = u;
    }
}

// ---------------------------------------------------------------------------
// K2: bin edges by destination row (indices are int32 per JAX default x64-off).
// ---------------------------------------------------------------------------
__global__ __launch_bounds__(256) void k_place(
    const int* __restrict__ rows, const int* __restrict__ cols, int n_edges)
{
    const int i = blockIdx.x * 256 + threadIdx.x;
    if (i >= n_edges) return;
    int r = rows[i], c = cols[i];
    r = min(max(r, 0), N_NODES - 1);
    c = min(max(c, 0), N_NODES - 1);
    const int slot = atomicAdd(&g_cnt[r], 1);
    if (slot < CAP) {
        g_bin[(size_t)r * CAP + slot] = c;
    } else {
        const int o = atomicAdd(&g_ovf_cnt, 1);
        g_ovf[2 * o] = r;
        g_ovf[2 * o + 1] = c;
    }
}

// ---------------------------------------------------------------------------
// K3: gather + finalize. Warp per node, fp16 I-rows (256B each), MLP=8:
//     AI = sum I[col];  dS = -beta*AI*S ; dI = -dS - gamma*I (= out[2]).
// ---------------------------------------------------------------------------
__global__ __launch_bounds__(256) void k_gather_final(
    const float* __restrict__ x, float* __restrict__ out)
{
    const int node = (blockIdx.x * 256 + threadIdx.x) >> 5;
    if (node >= N_NODES) return;
    const int lane = threadIdx.x & 31;

    const int d = min(g_cnt[node], CAP);
    const int* __restrict__ bin = g_bin + (size_t)node * CAP;
    const uint2* __restrict__ Ih = reinterpret_cast<const uint2*>(g_Ih);

    float4 a = make_float4(0.f, 0.f, 0.f, 0.f);
    int i = 0;
    for (; i + 8 <= d; i += 8) {      // 8 outstanding 256B L2 loads per warp
        int c[8];
        #pragma unroll
        for (int k = 0; k < 8; ++k) c[k] = __ldg(&bin[i + k]);
        uint2 u[8];
        #pragma unroll
        for (int k = 0; k < 8; ++k) u[k] = Ih[(size_t)c[k] * 32 + lane];
        #pragma unroll
        for (int k = 0; k < 8; ++k) {
            const float2 f0 = __half22float2(*reinterpret_cast<__half2*>(&u[k].x));
            const float2 f1 = __half22float2(*reinterpret_cast<__half2*>(&u[k].y));
            a.x += f0.x; a.y += f0.y; a.z += f1.x; a.w += f1.y;
        }
    }
    if (i + 4 <= d) {
        int c[4];
        #pragma unroll
        for (int k = 0; k < 4; ++k) c[k] = __ldg(&bin[i + k]);
        uint2 u[4];
        #pragma unroll
        for (int k = 0; k < 4; ++k) u[k] = Ih[(size_t)c[k] * 32 + lane];
        #pragma unroll
        for (int k = 0; k < 4; ++k) {
            const float2 f0 = __half22float2(*reinterpret_cast<__half2*>(&u[k].x));
            const float2 f1 = __half22float2(*reinterpret_cast<__half2*>(&u[k].y));
            a.x += f0.x; a.y += f0.y; a.z += f1.x; a.w += f1.y;
        }
        i += 4;
    }
    for (; i < d; ++i) {
        uint2 u = Ih[(size_t)__ldg(&bin[i]) * 32 + lane];
        const float2 f0 = __half22float2(*reinterpret_cast<__half2*>(&u.x));
        const float2 f1 = __half22float2(*reinterpret_cast<__half2*>(&u.y));
        a.x += f0.x; a.y += f0.y; a.z += f1.x; a.w += f1.y;
    }

    const float beta = x[((size_t)3 * N_NODES + node) * HIDDEN];
    const size_t fo = (size_t)node * 32 + lane;
    const float4 S4 = reinterpret_cast<const float4*>(g_S)[fo];
    const float4 G4 = reinterpret_cast<const float4*>(
        out + (size_t)2 * N_NODES * HIDDEN)[fo];

    float4 dS, dI;
    dS.x = -beta * a.x * S4.x;  dI.x = -dS.x - G4.x;
    dS.y = -beta * a.y * S4.y;  dI.y = -dS.y - G4.y;
    dS.z = -beta * a.z * S4.z;  dI.z = -dS.z - G4.z;
    dS.w = -beta * a.w * S4.w;  dI.w = -dS.w - G4.w;

    reinterpret_cast<float4*>(out)[fo] = dS;
    reinterpret_cast<float4*>(out + (size_t)N_NODES * HIDDEN)[fo] = dI;
}

// ---------------------------------------------------------------------------
// K4: overflow fix-up (expected empty; fp32 g_I) + re-zero counters.
// ---------------------------------------------------------------------------
__global__ __launch_bounds__(256) void k_fix(
    const float* __restrict__ x, float* __restrict__ out)
{
    if (blockIdx.x == 0) {
        const int n = g_ovf_cnt;
        if (n > 0) {
            const long long total = (long long)n * HIDDEN;
            for (long long idx = threadIdx.x; idx < total; idx += 256) {
                const int e = (int)(idx >> 7);
                const int j = (int)(idx & 127);
                const int r = g_ovf[2 * e];
                const int c = g_ovf[2 * e + 1];
                const float v = g_I[(size_t)c * HIDDEN + j];
                const float beta = x[((size_t)3 * N_NODES + r) * HIDDEN];
                const float delta = -beta * v * g_S[(size_t)r * HIDDEN + j];
                atomicAdd(&out[(size_t)r * HIDDEN + j], delta);
                atomicAdd(&out[(size_t)N_NODES * HIDDEN + (size_t)r * HIDDEN + j], -delta);
            }
        }
        __syncthreads();
        if (threadIdx.x == 0) g_ovf_cnt = 0;
    }
    for (int i = blockIdx.x * 256 + threadIdx.x; i < N_NODES;
         i += gridDim.x * 256) {
        g_cnt[i] = 0;
    }
}

// ---------------------------------------------------------------------------
extern "C" void kernel_launch(void* const* d_in, const int* in_sizes, int n_in,
                              void* d_out, int out_size)
{
    const float* x    = (const float*)d_in[0];
    const float* W    = (const float*)d_in[1];
    const float* b    = (const float*)d_in[2];
    const int*   rows = (const int*)d_in[3];
    const int*   cols = (const int*)d_in[4];
    float*       out  = (float*)d_out;

    const int n_edges = in_sizes[3];

    const size_t smem = (size_t)SM_U32 * sizeof(uint32_t);
    cudaFuncSetAttribute(k_gemm, cudaFuncAttributeMaxDynamicSharedMemorySize,
                         (int)smem);

    k_place<<<(n_edges + 255) / 256, 256>>>(rows, cols, n_edges);

    const int gemm_blocks = (N_NODES + NPB - 1) / NPB;
    k_gemm<<<gemm_blocks, 512, smem>>>(x, W, b, out);

    k_mirror<<<512, 256>>>();

    const int gf_blocks = (N_NODES * 32 + 255) / 256;  // warp per node
    k_gather_final<<<gf_blocks, 256>>>(x, out);

    k_fix<<<128, 256>>>(x, out);
}

// round 15
// speedup vs baseline: 2.5521x; 1.2671x over previous
#include <cuda_runtime.h>
#include <cuda_fp16.h>
#include <cstdint>

#define N_NODES 100000
#define HIDDEN  128
#define NPB     256   // nodes per CTA in GEMM kernel
#define CAP     48    // per-node edge bin capacity (Poisson mean 16; P(>=48)~1e-10)

// Scratch (device globals — allocation-free rule).
// INVARIANT: g_cnt[] and g_ovf_cnt are ZERO at kernel_launch entry
// (zero-init at module load; re-zeroed at the end of every call by k_fix).
__device__ __align__(16) float   g_S  [(size_t)N_NODES * HIDDEN];
__device__ __align__(16) __half2 g_Ih [(size_t)N_NODES * (HIDDEN / 2)];
__device__ int   g_cnt[N_NODES];
__device__ int   g_bin[(size_t)N_NODES * CAP];
__device__ int   g_ovf_cnt;
__device__ int   g_ovf[2 * 1600000];

__device__ __forceinline__ float sigmoidf(float v) {
    return 1.f / (1.f + __expf(-v));
}
// fp16 MMA m16n8k16, fp32 accumulate. Same fragment index scheme as the
// validated tf32 m16n8k8 path (groupID = lane>>2 rows, threadID = lane&3 k),
// with k packed as half2 per register.
__device__ __forceinline__ void mma_f16(float* c, uint32_t a0, uint32_t a1,
                                        uint32_t a2, uint32_t a3,
                                        uint32_t b0, uint32_t b1) {
    asm volatile(
        "mma.sync.aligned.m16n8k16.row.col.f32.f16.f16.f32 "
        "{%0,%1,%2,%3}, {%4,%5,%6,%7}, {%8,%9}, {%0,%1,%2,%3};"
        : "+f"(c[0]), "+f"(c[1]), "+f"(c[2]), "+f"(c[3])
        : "r"(a0), "r"(a1), "r"(a2), "r"(a3), "r"(b0), "r"(b1));
}

// Shared layout (uint32 = half2 elements), pitch 68 u32 per 128-half row:
//   xh [256][68]  node-major fp16 x tile   (A row-major: A[m][k])
//   Wh [128][68]  o-major fp16 W           (B col-major: B[n][k])
//   sgam[256], sbias[128] as floats
// Bank check (lane -> addr%32 = 4*grp + qk + const): conflict-free.
#define XH_SZ   (256 * 68)
#define WH_SZ   (128 * 68)
#define SM_U32  (XH_SZ + WH_SZ + 256 + 128)

// ---------------------------------------------------------------------------
// K1: fp16 mma.sync sigmoid-GEMM. 512 threads = 16 warps; warp w computes
// nodes [w*16, w*16+16) x all 128 outputs, K=128 in 8 k16-steps.
// Fuses: g_S (fp32), g_Ih (fp16, direct), out[2] = gamma*I, out[3] = 0.
// ---------------------------------------------------------------------------
__global__ __launch_bounds__(512, 1) void k_gemm(
    const float* __restrict__ x, const float* __restrict__ W,
    const float* __restrict__ b, float* __restrict__ out)
{
    extern __shared__ uint32_t sh[];
    uint32_t* xh    = sh;
    uint32_t* Wh    = sh + XH_SZ;
    float*    sgam  = reinterpret_cast<float*>(sh + XH_SZ + WH_SZ);
    float*    sbias = sgam + 256;

    const int tid  = threadIdx.x;
    const int warp = tid >> 5;
    const int lane = tid & 31;
    const int grp  = lane >> 2;   // 0..7
    const int qk   = lane & 3;    // 0..3
    const int base = blockIdx.x * NPB;
    const int nn   = min(NPB, N_NODES - base);
    const int m0   = warp * 16;

    // Wh[o*68 + k2] = half2(W[o*128 + 2k2], W[o*128 + 2k2+1])
    {
        const float2* Wsrc = reinterpret_cast<const float2*>(W);
        for (int idx = tid; idx < HIDDEN * 64; idx += 512) {
            const int o = idx >> 6, k2 = idx & 63;
            const float2 v = Wsrc[idx];
            const __half2 h = __floats2half2_rn(v.x, v.y);
            Wh[o * 68 + k2] = *reinterpret_cast<const unsigned*>(&h);
        }
    }
    if (tid < HIDDEN) sbias[tid] = b[tid];
    // gamma = x[3, node, 1]
    for (int n = tid; n < NPB; n += 512) {
        sgam[n] = (n < nn)
            ? x[((size_t)3 * N_NODES + base + n) * HIDDEN + 1] : 0.f;
    }

    for (int s = 0; s < 2; ++s) {
        // xh[n*68 + k2] = half2 of x[s, base+n, 2k2..2k2+1]; rows >= nn read
        // into the next s-slice (in-bounds of x, results discarded).
        const float2* xsrc = reinterpret_cast<const float2*>(
            x + ((size_t)s * N_NODES + base) * HIDDEN);
        __syncthreads();   // previous-iter consumers done before overwrite
        for (int idx = tid; idx < NPB * 64; idx += 512) {
            const int n = idx >> 6, k2 = idx & 63;
            const float2 v = xsrc[idx];
            const __half2 h = __floats2half2_rn(v.x, v.y);
            xh[n * 68 + k2] = *reinterpret_cast<const unsigned*>(&h);
        }
        __syncthreads();

        float acc[16][4];
        #pragma unroll
        for (int nb = 0; nb < 16; ++nb)
            #pragma unroll
            for (int i = 0; i < 4; ++i) acc[nb][i] = 0.f;

        const uint32_t* xrow0 = xh + (m0 + grp) * 68;       // rows m0+grp
        const uint32_t* xrow1 = xrow0 + 8 * 68;             // rows m0+grp+8

        #pragma unroll
        for (int k0 = 0; k0 < 8; ++k0) {
            const int kb = k0 * 8;                           // u32 (half2) base
            const uint32_t a0 = xrow0[kb + qk];              // (r0,   k 2qk..)
            const uint32_t a1 = xrow1[kb + qk];              // (r0+8, k 2qk..)
            const uint32_t a2 = xrow0[kb + qk + 4];          // (r0,   k 2qk+8..)
            const uint32_t a3 = xrow1[kb + qk + 4];          // (r0+8, k 2qk+8..)
            #pragma unroll
            for (int nb = 0; nb < 16; ++nb) {
                const uint32_t* wrow = Wh + (nb * 8 + grp) * 68 + kb;
                mma_f16(acc[nb], a0, a1, a2, a3, wrow[qk], wrow[qk + 4]);
            }
        }

        // Epilogue: thread owns rows r0 = m0+grp, r1 = r0+8;
        // per nb, cols nb*8 + 2*qk (+1): float2 / half2 stores.
        const int r0 = m0 + grp, r1 = r0 + 8;
        const float gm0 = sgam[r0], gm1 = sgam[r1];
        #pragma unroll
        for (int nb = 0; nb < 16; ++nb) {
            const int col = nb * 8 + 2 * qk;
            const float b0 = sbias[col], b1 = sbias[col + 1];
            const float v00 = sigmoidf(acc[nb][0] + b0);
            const float v01 = sigmoidf(acc[nb][1] + b1);
            const float v10 = sigmoidf(acc[nb][2] + b0);
            const float v11 = sigmoidf(acc[nb][3] + b1);
            const size_t o0 = ((size_t)(base + r0)) * HIDDEN + col;
            const size_t o1 = ((size_t)(base + r1)) * HIDDEN + col;
            if (s == 0) {
                if (r0 < nn) *reinterpret_cast<float2*>(&g_S[o0]) = make_float2(v00, v01);
                if (r1 < nn) *reinterpret_cast<float2*>(&g_S[o1]) = make_float2(v10, v11);
            } else {
                if (r0 < nn) {
                    g_Ih[((size_t)(base + r0)) * 64 + nb * 4 + qk]
                        = __floats2half2_rn(v00, v01);
                    *reinterpret_cast<float2*>(&out[(size_t)2 * N_NODES * HIDDEN + o0])
                        = make_float2(gm0 * v00, gm0 * v01);
                    *reinterpret_cast<float2*>(&out[(size_t)3 * N_NODES * HIDDEN + o0])
                        = make_float2(0.f, 0.f);
                }
                if (r1 < nn) {
                    g_Ih[((size_t)(base + r1)) * 64 + nb * 4 + qk]
                        = __floats2half2_rn(v10, v11);
                    *reinterpret_cast<float2*>(&out[(size_t)2 * N_NODES * HIDDEN + o1])
                        = make_float2(gm1 * v10, gm1 * v11);
                    *reinterpret_cast<float2*>(&out[(size_t)3 * N_NODES * HIDDEN + o1])
                        = make_float2(0.f, 0.f);
                }
            }
        }
    }
}

// ---------------------------------------------------------------------------
// K2: bin edges by destination row (indices are int32 per JAX default x64-off).
// ---------------------------------------------------------------------------
__global__ __launch_bounds__(256) void k_place(
    const int* __restrict__ rows, const int* __restrict__ cols, int n_edges)
{
    const int i = blockIdx.x * 256 + threadIdx.x;
    if (i >= n_edges) return;
    int r = rows[i], c = cols[i];
    r = min(max(r, 0), N_NODES - 1);
    c = min(max(c, 0), N_NODES - 1);
    const int slot = atomicAdd(&g_cnt[r], 1);
    if (slot < CAP) {
        g_bin[(size_t)r * CAP + slot] = c;
    } else {
        const int o = atomicAdd(&g_ovf_cnt, 1);
        g_ovf[2 * o] = r;
        g_ovf[2 * o + 1] = c;
    }
}

// ---------------------------------------------------------------------------
// K3: gather + finalize (r14-proven). Warp per node, fp16 I-rows, MLP=8:
//     AI = sum I[col];  dS = -beta*AI*S ; dI = -dS - gamma*I (= out[2]).
// ---------------------------------------------------------------------------
__global__ __launch_bounds__(256) void k_gather_final(
    const float* __restrict__ x, float* __restrict__ out)
{
    const int node = (blockIdx.x * 256 + threadIdx.x) >> 5;
    if (node >= N_NODES) return;
    const int lane = threadIdx.x & 31;

    const int d = min(g_cnt[node], CAP);
    const int* __restrict__ bin = g_bin + (size_t)node * CAP;
    const uint2* __restrict__ Ih = reinterpret_cast<const uint2*>(g_Ih);

    float4 a = make_float4(0.f, 0.f, 0.f, 0.f);
    int i = 0;
    for (; i + 8 <= d; i += 8) {      // 8 outstanding 256B L2 loads per warp
        int c[8];
        #pragma unroll
        for (int k = 0; k < 8; ++k) c[k] = __ldg(&bin[i + k]);
        uint2 u[8];
        #pragma unroll
        for (int k = 0; k < 8; ++k) u[k] = Ih[(size_t)c[k] * 32 + lane];
        #pragma unroll
        for (int k = 0; k < 8; ++k) {
            const float2 f0 = __half22float2(*reinterpret_cast<__half2*>(&u[k].x));
            const float2 f1 = __half22float2(*reinterpret_cast<__half2*>(&u[k].y));
            a.x += f0.x; a.y += f0.y; a.z += f1.x; a.w += f1.y;
        }
    }
    if (i + 4 <= d) {
        int c[4];
        #pragma unroll
        for (int k = 0; k < 4; ++k) c[k] = __ldg(&bin[i + k]);
        uint2 u[4];
        #pragma unroll
        for (int k = 0; k < 4; ++k) u[k] = Ih[(size_t)c[k] * 32 + lane];
        #pragma unroll
        for (int k = 0; k < 4; ++k) {
            const float2 f0 = __half22float2(*reinterpret_cast<__half2*>(&u[k].x));
            const float2 f1 = __half22float2(*reinterpret_cast<__half2*>(&u[k].y));
            a.x += f0.x; a.y += f0.y; a.z += f1.x; a.w += f1.y;
        }
        i += 4;
    }
    for (; i < d; ++i) {
        uint2 u = Ih[(size_t)__ldg(&bin[i]) * 32 + lane];
        const float2 f0 = __half22float2(*reinterpret_cast<__half2*>(&u.x));
        const float2 f1 = __half22float2(*reinterpret_cast<__half2*>(&u.y));
        a.x += f0.x; a.y += f0.y; a.z += f1.x; a.w += f1.y;
    }

    const float beta = x[((size_t)3 * N_NODES + node) * HIDDEN];
    const size_t fo = (size_t)node * 32 + lane;
    const float4 S4 = reinterpret_cast<const float4*>(g_S)[fo];
    const float4 G4 = reinterpret_cast<const float4*>(
        out + (size_t)2 * N_NODES * HIDDEN)[fo];

    float4 dS, dI;
    dS.x = -beta * a.x * S4.x;  dI.x = -dS.x - G4.x;
    dS.y = -beta * a.y * S4.y;  dI.y = -dS.y - G4.y;
    dS.z = -beta * a.z * S4.z;  dI.z = -dS.z - G4.z;
    dS.w = -beta * a.w * S4.w;  dI.w = -dS.w - G4.w;

    reinterpret_cast<float4*>(out)[fo] = dS;
    reinterpret_cast<float4*>(out + (size_t)N_NODES * HIDDEN)[fo] = dI;
}

// ---------------------------------------------------------------------------
// K4: overflow fix-up (expected empty; reads fp16 I) + re-zero counters.
// ---------------------------------------------------------------------------
__global__ __launch_bounds__(256) void k_fix(
    const float* __restrict__ x, float* __restrict__ out)
{
    if (blockIdx.x == 0) {
        const int n = g_ovf_cnt;
        if (n > 0) {
            const __half* Ihs = reinterpret_cast<const __half*>(g_Ih);
            const long long total = (long long)n * HIDDEN;
            for (long long idx = threadIdx.x; idx < total; idx += 256) {
                const int e = (int)(idx >> 7);
                const int j = (int)(idx & 127);
                const int r = g_ovf[2 * e];
                const int c = g_ovf[2 * e + 1];
                const float v = __half2float(Ihs[(size_t)c * HIDDEN + j]);
                const float beta = x[((size_t)3 * N_NODES + r) * HIDDEN];
                const float delta = -beta * v * g_S[(size_t)r * HIDDEN + j];
                atomicAdd(&out[(size_t)r * HIDDEN + j], delta);
                atomicAdd(&out[(size_t)N_NODES * HIDDEN + (size_t)r * HIDDEN + j], -delta);
            }
        }
        __syncthreads();
        if (threadIdx.x == 0) g_ovf_cnt = 0;
    }
    for (int i = blockIdx.x * 256 + threadIdx.x; i < N_NODES;
         i += gridDim.x * 256) {
        g_cnt[i] = 0;
    }
}

// ---------------------------------------------------------------------------
extern "C" void kernel_launch(void* const* d_in, const int* in_sizes, int n_in,
                              void* d_out, int out_size)
{
    const float* x    = (const float*)d_in[0];
    const float* W    = (const float*)d_in[1];
    const float* b    = (const float*)d_in[2];
    const int*   rows = (const int*)d_in[3];
    const int*   cols = (const int*)d_in[4];
    float*       out  = (float*)d_out;

    const int n_edges = in_sizes[3];

    const size_t smem = (size_t)SM_U32 * sizeof(uint32_t);
    cudaFuncSetAttribute(k_gemm, cudaFuncAttributeMaxDynamicSharedMemorySize,
                         (int)smem);

    k_place<<<(n_edges + 255) / 256, 256>>>(rows, cols, n_edges);

    const int gemm_blocks = (N_NODES + NPB - 1) / NPB;
    k_gemm<<<gemm_blocks, 512, smem>>>(x, W, b, out);

    const int gf_blocks = (N_NODES * 32 + 255) / 256;  // warp per node
    k_gather_final<<<gf_blocks, 256>>>(x, out);

    k_fix<<<128, 256>>>(x, out);
}

// round 16
// speedup vs baseline: 2.5584x; 1.0025x over previous
#include <cuda_runtime.h>
#include <cuda_fp16.h>
#include <cstdint>

#define N_NODES 100000
#define HIDDEN  128
#define NPB     256   // nodes per CTA in GEMM kernel
#define CAP     48    // per-node edge bin capacity (Poisson mean 16; P(>=48)~1e-10)
#define PLACE_BLKS 96 // leading blocks of k_gemm that do edge binning

// Scratch (device globals — allocation-free rule).
// INVARIANT: g_cnt[] and g_ovf_cnt are ZERO at kernel_launch entry
// (zero-init at module load; re-zeroed at the end of every call by k_fix).
__device__ __align__(16) __half2 g_Sh [(size_t)N_NODES * (HIDDEN / 2)];
__device__ __align__(16) __half2 g_Ih [(size_t)N_NODES * (HIDDEN / 2)];
__device__ int   g_cnt[N_NODES];
__device__ int   g_bin[(size_t)N_NODES * CAP];
__device__ int   g_ovf_cnt;
__device__ int   g_ovf[2 * 1600000];

__device__ __forceinline__ float sigmoidf(float v) {
    return 1.f / (1.f + __expf(-v));
}
// fp16 MMA m16n8k16, fp32 accumulate (validated r15).
__device__ __forceinline__ void mma_f16(float* c, uint32_t a0, uint32_t a1,
                                        uint32_t a2, uint32_t a3,
                                        uint32_t b0, uint32_t b1) {
    asm volatile(
        "mma.sync.aligned.m16n8k16.row.col.f32.f16.f16.f32 "
        "{%0,%1,%2,%3}, {%4,%5,%6,%7}, {%8,%9}, {%0,%1,%2,%3};"
        : "+f"(c[0]), "+f"(c[1]), "+f"(c[2]), "+f"(c[3])
        : "r"(a0), "r"(a1), "r"(a2), "r"(a3), "r"(b0), "r"(b1));
}

// Shared layout (uint32 = half2 elements), pitch 68 u32 per 128-half row:
//   xh [256][68]  node-major fp16 x tile   (A row-major: A[m][k])
//   Wh [128][68]  o-major fp16 W           (B col-major: B[n][k])
//   sgam[256], sbias[128] as floats
#define XH_SZ   (256 * 68)
#define WH_SZ   (128 * 68)
#define SM_U32  (XH_SZ + WH_SZ + 256 + 128)

// ---------------------------------------------------------------------------
// K1: fused kernel. Blocks [0, PLACE_BLKS): edge binning (overlaps with GEMM
// waves). Blocks >= PLACE_BLKS: fp16 mma.sync sigmoid-GEMM (r15-proven path),
// fusing g_Sh (fp16), g_Ih (fp16), out[2] = gamma*I, out[3] = 0.
// ---------------------------------------------------------------------------
__global__ __launch_bounds__(512, 1) void k_gemm(
    const float* __restrict__ x, const float* __restrict__ W,
    const float* __restrict__ b, float* __restrict__ out,
    const int* __restrict__ rows, const int* __restrict__ cols, int n_edges)
{
    if (blockIdx.x < PLACE_BLKS) {
        // ---- edge binning path (no smem, no MMA) ----
        const int stride = PLACE_BLKS * 512;
        #pragma unroll 4
        for (int e = blockIdx.x * 512 + threadIdx.x; e < n_edges; e += stride) {
            int r = rows[e], c = cols[e];
            r = min(max(r, 0), N_NODES - 1);
            c = min(max(c, 0), N_NODES - 1);
            const int slot = atomicAdd(&g_cnt[r], 1);
            if (slot < CAP) {
                g_bin[(size_t)r * CAP + slot] = c;
            } else {
                const int o = atomicAdd(&g_ovf_cnt, 1);
                g_ovf[2 * o] = r;
                g_ovf[2 * o + 1] = c;
            }
        }
        return;
    }

    // ---- GEMM path ----
    extern __shared__ uint32_t sh[];
    uint32_t* xh    = sh;
    uint32_t* Wh    = sh + XH_SZ;
    float*    sgam  = reinterpret_cast<float*>(sh + XH_SZ + WH_SZ);
    float*    sbias = sgam + 256;

    const int tid  = threadIdx.x;
    const int warp = tid >> 5;
    const int lane = tid & 31;
    const int grp  = lane >> 2;   // 0..7
    const int qk   = lane & 3;    // 0..3
    const int base = (blockIdx.x - PLACE_BLKS) * NPB;
    const int nn   = min(NPB, N_NODES - base);
    const int m0   = warp * 16;

    // Wh[o*68 + k2] = half2(W[o*128 + 2k2], W[o*128 + 2k2+1])
    {
        const float2* Wsrc = reinterpret_cast<const float2*>(W);
        for (int idx = tid; idx < HIDDEN * 64; idx += 512) {
            const int o = idx >> 6, k2 = idx & 63;
            const float2 v = Wsrc[idx];
            const __half2 h = __floats2half2_rn(v.x, v.y);
            Wh[o * 68 + k2] = *reinterpret_cast<const unsigned*>(&h);
        }
    }
    if (tid < HIDDEN) sbias[tid] = b[tid];
    // gamma = x[3, node, 1]
    for (int n = tid; n < NPB; n += 512) {
        sgam[n] = (n < nn)
            ? x[((size_t)3 * N_NODES + base + n) * HIDDEN + 1] : 0.f;
    }

    for (int s = 0; s < 2; ++s) {
        // xh[n*68 + k2] = half2 of x[s, base+n, 2k2..2k2+1]; rows >= nn read
        // into the next s-slice (in-bounds of x, results discarded).
        const float2* xsrc = reinterpret_cast<const float2*>(
            x + ((size_t)s * N_NODES + base) * HIDDEN);
        __syncthreads();   // previous-iter consumers done before overwrite
        for (int idx = tid; idx < NPB * 64; idx += 512) {
            const int n = idx >> 6, k2 = idx & 63;
            const float2 v = xsrc[idx];
            const __half2 h = __floats2half2_rn(v.x, v.y);
            xh[n * 68 + k2] = *reinterpret_cast<const unsigned*>(&h);
        }
        __syncthreads();

        float acc[16][4];
        #pragma unroll
        for (int nb = 0; nb < 16; ++nb)
            #pragma unroll
            for (int i = 0; i < 4; ++i) acc[nb][i] = 0.f;

        const uint32_t* xrow0 = xh + (m0 + grp) * 68;       // rows m0+grp
        const uint32_t* xrow1 = xrow0 + 8 * 68;             // rows m0+grp+8

        #pragma unroll
        for (int k0 = 0; k0 < 8; ++k0) {
            const int kb = k0 * 8;                           // u32 (half2) base
            const uint32_t a0 = xrow0[kb + qk];
            const uint32_t a1 = xrow1[kb + qk];
            const uint32_t a2 = xrow0[kb + qk + 4];
            const uint32_t a3 = xrow1[kb + qk + 4];
            #pragma unroll
            for (int nb = 0; nb < 16; ++nb) {
                const uint32_t* wrow = Wh + (nb * 8 + grp) * 68 + kb;
                mma_f16(acc[nb], a0, a1, a2, a3, wrow[qk], wrow[qk + 4]);
            }
        }

        // Epilogue: thread owns rows r0 = m0+grp, r1 = r0+8;
        // per nb, cols nb*8 + 2*qk (+1): half2 / float2 stores.
        const int r0 = m0 + grp, r1 = r0 + 8;
        const float gm0 = sgam[r0], gm1 = sgam[r1];
        #pragma unroll
        for (int nb = 0; nb < 16; ++nb) {
            const int col = nb * 8 + 2 * qk;
            const float b0 = sbias[col], b1 = sbias[col + 1];
            const float v00 = sigmoidf(acc[nb][0] + b0);
            const float v01 = sigmoidf(acc[nb][1] + b1);
            const float v10 = sigmoidf(acc[nb][2] + b0);
            const float v11 = sigmoidf(acc[nb][3] + b1);
            const int h2i = nb * 4 + qk;   // half2 index within row
            if (s == 0) {
                if (r0 < nn) g_Sh[((size_t)(base + r0)) * 64 + h2i]
                    = __floats2half2_rn(v00, v01);
                if (r1 < nn) g_Sh[((size_t)(base + r1)) * 64 + h2i]
                    = __floats2half2_rn(v10, v11);
            } else {
                const size_t o0 = ((size_t)(base + r0)) * HIDDEN + col;
                const size_t o1 = ((size_t)(base + r1)) * HIDDEN + col;
                if (r0 < nn) {
                    g_Ih[((size_t)(base + r0)) * 64 + h2i]
                        = __floats2half2_rn(v00, v01);
                    *reinterpret_cast<float2*>(&out[(size_t)2 * N_NODES * HIDDEN + o0])
                        = make_float2(gm0 * v00, gm0 * v01);
                    *reinterpret_cast<float2*>(&out[(size_t)3 * N_NODES * HIDDEN + o0])
                        = make_float2(0.f, 0.f);
                }
                if (r1 < nn) {
                    g_Ih[((size_t)(base + r1)) * 64 + h2i]
                        = __floats2half2_rn(v10, v11);
                    *reinterpret_cast<float2*>(&out[(size_t)2 * N_NODES * HIDDEN + o1])
                        = make_float2(gm1 * v10, gm1 * v11);
                    *reinterpret_cast<float2*>(&out[(size_t)3 * N_NODES * HIDDEN + o1])
                        = make_float2(0.f, 0.f);
                }
            }
        }
    }
}

// ---------------------------------------------------------------------------
// K2: gather + finalize. Warp per node, fp16 I/S rows, MLP=8:
//     AI = sum I[col];  dS = -beta*AI*S ; dI = -dS - gamma*I_own.
//     beta/gamma via one float2 load; gamma*I recomputed from own g_Ih row.
// ---------------------------------------------------------------------------
__global__ __launch_bounds__(256) void k_gather_final(
    const float* __restrict__ x, float* __restrict__ out)
{
    const int node = (blockIdx.x * 256 + threadIdx.x) >> 5;
    if (node >= N_NODES) return;
    const int lane = threadIdx.x & 31;

    const int d = min(g_cnt[node], CAP);
    const int* __restrict__ bin = g_bin + (size_t)node * CAP;
    const uint2* __restrict__ Ih = reinterpret_cast<const uint2*>(g_Ih);
    const uint2* __restrict__ Sh = reinterpret_cast<const uint2*>(g_Sh);

    float4 a = make_float4(0.f, 0.f, 0.f, 0.f);
    int i = 0;
    for (; i + 8 <= d; i += 8) {      // 8 outstanding 256B L2 loads per warp
        int c[8];
        #pragma unroll
        for (int k = 0; k < 8; ++k) c[k] = __ldg(&bin[i + k]);
        uint2 u[8];
        #pragma unroll
        for (int k = 0; k < 8; ++k) u[k] = Ih[(size_t)c[k] * 32 + lane];
        #pragma unroll
        for (int k = 0; k < 8; ++k) {
            const float2 f0 = __half22float2(*reinterpret_cast<__half2*>(&u[k].x));
            const float2 f1 = __half22float2(*reinterpret_cast<__half2*>(&u[k].y));
            a.x += f0.x; a.y += f0.y; a.z += f1.x; a.w += f1.y;
        }
    }
    if (i + 4 <= d) {
        int c[4];
        #pragma unroll
        for (int k = 0; k < 4; ++k) c[k] = __ldg(&bin[i + k]);
        uint2 u[4];
        #pragma unroll
        for (int k = 0; k < 4; ++k) u[k] = Ih[(size_t)c[k] * 32 + lane];
        #pragma unroll
        for (int k = 0; k < 4; ++k) {
            const float2 f0 = __half22float2(*reinterpret_cast<__half2*>(&u[k].x));
            const float2 f1 = __half22float2(*reinterpret_cast<__half2*>(&u[k].y));
            a.x += f0.x; a.y += f0.y; a.z += f1.x; a.w += f1.y;
        }
        i += 4;
    }
    for (; i < d; ++i) {
        uint2 u = Ih[(size_t)__ldg(&bin[i]) * 32 + lane];
        const float2 f0 = __half22float2(*reinterpret_cast<__half2*>(&u.x));
        const float2 f1 = __half22float2(*reinterpret_cast<__half2*>(&u.y));
        a.x += f0.x; a.y += f0.y; a.z += f1.x; a.w += f1.y;
    }

    // beta = x[3,node,0], gamma = x[3,node,1] — one float2 broadcast load
    const float2 bg = *reinterpret_cast<const float2*>(
        &x[((size_t)3 * N_NODES + node) * HIDDEN]);
    const float beta = bg.x, gamma = bg.y;

    const size_t fo = (size_t)node * 32 + lane;
    uint2 su = Sh[fo];
    const float2 s0 = __half22float2(*reinterpret_cast<__half2*>(&su.x));
    const float2 s1 = __half22float2(*reinterpret_cast<__half2*>(&su.y));
    uint2 gu = Ih[fo];
    const float2 g0 = __half22float2(*reinterpret_cast<__half2*>(&gu.x));
    const float2 g1 = __half22float2(*reinterpret_cast<__half2*>(&gu.y));

    float4 dS, dI;
    dS.x = -beta * a.x * s0.x;  dI.x = -dS.x - gamma * g0.x;
    dS.y = -beta * a.y * s0.y;  dI.y = -dS.y - gamma * g0.y;
    dS.z = -beta * a.z * s1.x;  dI.z = -dS.z - gamma * g1.x;
    dS.w = -beta * a.w * s1.y;  dI.w = -dS.w - gamma * g1.y;

    reinterpret_cast<float4*>(out)[fo] = dS;
    reinterpret_cast<float4*>(out + (size_t)N_NODES * HIDDEN)[fo] = dI;
}

// ---------------------------------------------------------------------------
// K3: overflow fix-up (expected empty; fp16 S/I) + re-zero counters.
// ---------------------------------------------------------------------------
__global__ __launch_bounds__(256) void k_fix(
    const float* __restrict__ x, float* __restrict__ out)
{
    if (blockIdx.x == 0) {
        const int n = g_ovf_cnt;
        if (n > 0) {
            const __half* Ihs = reinterpret_cast<const __half*>(g_Ih);
            const __half* Shs = reinterpret_cast<const __half*>(g_Sh);
            const long long total = (long long)n * HIDDEN;
            for (long long idx = threadIdx.x; idx < total; idx += 256) {
                const int e = (int)(idx >> 7);
                const int j = (int)(idx & 127);
                const int r = g_ovf[2 * e];
                const int c = g_ovf[2 * e + 1];
                const float v = __half2float(Ihs[(size_t)c * HIDDEN + j]);
                const float sv = __half2float(Shs[(size_t)r * HIDDEN + j]);
                const float beta = x[((size_t)3 * N_NODES + r) * HIDDEN];
                const float delta = -beta * v * sv;
                atomicAdd(&out[(size_t)r * HIDDEN + j], delta);
                atomicAdd(&out[(size_t)N_NODES * HIDDEN + (size_t)r * HIDDEN + j], -delta);
            }
        }
        __syncthreads();
        if (threadIdx.x == 0) g_ovf_cnt = 0;
    }
    for (int i = blockIdx.x * 256 + threadIdx.x; i < N_NODES;
         i += gridDim.x * 256) {
        g_cnt[i] = 0;
    }
}

// ---------------------------------------------------------------------------
extern "C" void kernel_launch(void* const* d_in, const int* in_sizes, int n_in,
                              void* d_out, int out_size)
{
    const float* x    = (const float*)d_in[0];
    const float* W    = (const float*)d_in[1];
    const float* b    = (const float*)d_in[2];
    const int*   rows = (const int*)d_in[3];
    const int*   cols = (const int*)d_in[4];
    float*       out  = (float*)d_out;

    const int n_edges = in_sizes[3];

    const size_t smem = (size_t)SM_U32 * sizeof(uint32_t);
    cudaFuncSetAttribute(k_gemm, cudaFuncAttributeMaxDynamicSharedMemorySize,
                         (int)smem);

    const int gemm_blocks = (N_NODES + NPB - 1) / NPB;
    k_gemm<<<PLACE_BLKS + gemm_blocks, 512, smem>>>(x, W, b, out,
                                                    rows, cols, n_edges);

    const int gf_blocks = (N_NODES * 32 + 255) / 256;  // warp per node
    k_gather_final<<<gf_blocks, 256>>>(x, out);

    k_fix<<<128, 256>>>(x, out);
}